// round 9
// baseline (speedup 1.0000x reference)
#include <cuda_runtime.h>

#define N_NODES 50000
#define N_EDGES 800000
#define QUADS   (N_EDGES / 4)
#define F 128
#define BM_WORDS ((N_NODES + 31) / 32)
#define NB 592
#define BS 128

// ---- scratch (static device arrays; no allocation allowed) ----
__device__ unsigned g_bm1[BM_WORDS];
__device__ unsigned g_bm2[BM_WORDS];
__device__ int   g_list1[N_NODES];
__device__ int   g_list2[512];
__device__ int   g_deg1[N_NODES];
__device__ int   g_deg2[N_NODES];
__device__ int2  g_elist1[N_EDGES];
__device__ int2  g_elist2[N_EDGES];
__device__ int   g_n1, g_n2, g_ne1, g_ne2;
__device__ float g_agg1[N_NODES * F];
__device__ float g_agg2[N_NODES * F];
__device__ float g_h1[N_NODES * F];
__device__ float g_h2[N_NODES * F];

// ---- device-wide barrier state (zero-initialized) ----
__device__ int      g_bar_arrive;
__device__ unsigned g_bar_gen;

// ---- shared memory union across phases ----
struct PassSmem { int cnt; int base; };
struct GemmSmem {
    int   rows[32];
    float invs[32];
    float As[32][36];
    float Bs[32][132];
};
union Smem {
    PassSmem pass;
    GemmSmem g;
    float    red[128];
};

__device__ __forceinline__ bool bm_test(const unsigned* bm, int n) {
    return (bm[n >> 5] >> (n & 31)) & 1u;
}

// Sense-reversing grid barrier. __threadfence() (gpu scope) on both sides:
// writer side publishes, reader side invalidates L1D (CCTL.IVALL on sm_103a).
__device__ __forceinline__ void grid_barrier() {
    __syncthreads();
    if (threadIdx.x == 0) {
        __threadfence();
        unsigned gen = atomicAdd(&g_bar_gen, 0u);
        if (atomicAdd(&g_bar_arrive, 1) == (int)gridDim.x - 1) {
            g_bar_arrive = 0;
            __threadfence();
            atomicAdd(&g_bar_gen, 1u);
        } else {
            while (atomicAdd(&g_bar_gen, 0u) == gen)
                __nanosleep(64);
        }
        __threadfence();
    }
    __syncthreads();
}

// ---------------- edge filter phase (hierarchical compaction, PROVEN body) ----
__device__ void pass_phase(Smem* sm,
                           const int* __restrict__ src, const int* __restrict__ dst,
                           const unsigned* __restrict__ bm,
                           int2* __restrict__ elist, int* __restrict__ ne,
                           int* __restrict__ deg, bool expand) {
    int tid  = threadIdx.x;
    int lane = tid & 31;
    for (int base = blockIdx.x * BS; base < QUADS; base += (int)gridDim.x * BS) {
        if (tid == 0) sm->pass.cnt = 0;
        __syncthreads();

        int i4 = base + tid;
        bool valid = (i4 < QUADS);
        int4 d4 = valid ? ((const int4*)dst)[i4] : make_int4(0, 0, 0, 0);
        int4 s4 = valid ? ((const int4*)src)[i4] : make_int4(0, 0, 0, 0);
        int dv[4] = {d4.x, d4.y, d4.z, d4.w};
        int sv[4] = {s4.x, s4.y, s4.z, s4.w};
        bool pass[4];
        int my = 0;
#pragma unroll
        for (int j = 0; j < 4; j++) {
            pass[j] = valid && bm_test(bm, dv[j]);
            my += pass[j] ? 1 : 0;
        }
        int scan = my;
#pragma unroll
        for (int d = 1; d < 32; d <<= 1) {
            int t = __shfl_up_sync(0xffffffff, scan, d);
            if (lane >= d) scan += t;
        }
        int wtotal = __shfl_sync(0xffffffff, scan, 31);
        int wbase = 0;
        if (lane == 31 && wtotal > 0) wbase = atomicAdd(&sm->pass.cnt, wtotal);
        wbase = __shfl_sync(0xffffffff, wbase, 31);
        int my_off = wbase + scan - my;
        __syncthreads();
        if (tid == 0) sm->pass.base = (sm->pass.cnt > 0) ? atomicAdd(ne, sm->pass.cnt) : 0;
        __syncthreads();
        int p = sm->pass.base + my_off;
#pragma unroll
        for (int j = 0; j < 4; j++) {
            if (pass[j]) {
                elist[p++] = make_int2(sv[j], dv[j]);
                atomicAdd(&deg[dv[j]], 1);
                if (expand) {
                    unsigned bit = 1u << (sv[j] & 31);
                    unsigned old = atomicOr(&g_bm1[sv[j] >> 5], bit);
                    if (!(old & bit)) {
                        int q = atomicAdd(&g_n1, 1);
                        g_list1[q] = sv[j];
                        g_deg1[sv[j]] = 0;
                    }
                }
            }
        }
        __syncthreads();
    }
}

// ---------------- zero agg rows for listed nodes (warp per node) ----------------
__device__ void zero_phase(const int* __restrict__ list, int count, float* __restrict__ agg) {
    int gw   = (blockIdx.x * BS + threadIdx.x) >> 5;
    int nw   = ((int)gridDim.x * BS) >> 5;
    int lane = threadIdx.x & 31;
    for (int w = gw; w < count; w += nw)
        ((float4*)agg)[list[w] * 32 + lane] = make_float4(0.f, 0.f, 0.f, 0.f);
}

// ---------------- edge aggregation: warp per edge, vector red (PROVEN) ---------
__device__ void agg_phase(const int2* __restrict__ elist, int ne,
                          const float* __restrict__ feat, float* __restrict__ agg) {
    int gw   = (blockIdx.x * BS + threadIdx.x) >> 5;
    int nw   = ((int)gridDim.x * BS) >> 5;
    int lane = threadIdx.x & 31;
    for (int j = gw; j < ne; j += nw) {
        int2 e = elist[j];
        float4 v = ((const float4*)feat)[e.x * 32 + lane];
        float* a = &agg[e.y * F + lane * 4];
        asm volatile("red.global.add.v4.f32 [%0], {%1, %2, %3, %4};"
                     :: "l"(a), "f"(v.x), "f"(v.y), "f"(v.z), "f"(v.w) : "memory");
    }
}

// ---------------- fused SAGE GEMM tile (PROVEN 128-thread 4x8 body) ------------
__device__ void gemm_tile(Smem* sm, int m0, int count,
                          const int* __restrict__ list,
                          const float* __restrict__ feat, const float* __restrict__ agg,
                          const int* __restrict__ deg,
                          const float* __restrict__ Ws, const float* __restrict__ Wn,
                          const float* __restrict__ bias, float* __restrict__ outp) {
    int tid = threadIdx.x;
    int r0  = (tid >> 4) * 4;
    int c0  = (tid & 15) * 8;

    if (tid < 32) {
        int nd = (m0 + tid < count) ? list[m0 + tid] : -1;
        sm->g.rows[tid] = nd;
        sm->g.invs[tid] = (nd >= 0) ? 1.0f / (float)max(deg[nd], 1) : 0.f;
    }
    __syncthreads();

    float acc[4][8];
#pragma unroll
    for (int m = 0; m < 4; m++)
#pragma unroll
        for (int n = 0; n < 8; n++) acc[m][n] = 0.f;

#pragma unroll 1
    for (int kt = 0; kt < 8; kt++) {
        const float* A = (kt < 4) ? feat : agg;
        const float* W = (kt < 4) ? Ws : Wn;
        int kb4 = (kt & 3) * 8;

#pragma unroll
        for (int i = 0; i < 2; i++) {
            int v   = tid + 128 * i;
            int row = v >> 3;
            int kq  = v & 7;
            int nd  = sm->g.rows[row];
            float4 a = make_float4(0.f, 0.f, 0.f, 0.f);
            if (nd >= 0) a = ((const float4*)A)[nd * 32 + kb4 + kq];
            float sc = (kt < 4) ? 1.0f : sm->g.invs[row];
            sm->g.As[kq * 4 + 0][row] = a.x * sc;
            sm->g.As[kq * 4 + 1][row] = a.y * sc;
            sm->g.As[kq * 4 + 2][row] = a.z * sc;
            sm->g.As[kq * 4 + 3][row] = a.w * sc;
        }
#pragma unroll
        for (int i = 0; i < 8; i++) {
            int v  = tid + 128 * i;
            int c  = v >> 3;
            int kq = v & 7;
            float4 w = ((const float4*)W)[c * 32 + kb4 + kq];
            sm->g.Bs[kq * 4 + 0][c] = w.x;
            sm->g.Bs[kq * 4 + 1][c] = w.y;
            sm->g.Bs[kq * 4 + 2][c] = w.z;
            sm->g.Bs[kq * 4 + 3][c] = w.w;
        }
        __syncthreads();

#pragma unroll
        for (int k = 0; k < 32; k++) {
            float4 a4 = *(const float4*)&sm->g.As[k][r0];
            float4 b0 = *(const float4*)&sm->g.Bs[k][c0];
            float4 b1 = *(const float4*)&sm->g.Bs[k][c0 + 4];
            float am[4] = {a4.x, a4.y, a4.z, a4.w};
            float bn[8] = {b0.x, b0.y, b0.z, b0.w, b1.x, b1.y, b1.z, b1.w};
#pragma unroll
            for (int m = 0; m < 4; m++)
#pragma unroll
                for (int n = 0; n < 8; n++)
                    acc[m][n] += am[m] * bn[n];
        }
        __syncthreads();
    }

    float bv[8];
#pragma unroll
    for (int n = 0; n < 8; n++) bv[n] = bias[c0 + n];

#pragma unroll
    for (int m = 0; m < 4; m++) {
        int nd = sm->g.rows[r0 + m];
        if (nd >= 0) {
            float4 o0, o1;
            o0.x = fmaxf(acc[m][0] + bv[0], 0.f);
            o0.y = fmaxf(acc[m][1] + bv[1], 0.f);
            o0.z = fmaxf(acc[m][2] + bv[2], 0.f);
            o0.w = fmaxf(acc[m][3] + bv[3], 0.f);
            o1.x = fmaxf(acc[m][4] + bv[4], 0.f);
            o1.y = fmaxf(acc[m][5] + bv[5], 0.f);
            o1.z = fmaxf(acc[m][6] + bv[6], 0.f);
            o1.w = fmaxf(acc[m][7] + bv[7], 0.f);
            ((float4*)outp)[nd * 32 + (c0 >> 2)]     = o0;
            ((float4*)outp)[nd * 32 + (c0 >> 2) + 1] = o1;
        }
    }
    __syncthreads();
}

// ---------------- the persistent megakernel ----------------
__global__ void __launch_bounds__(BS, 4) mega_kernel(
    const float* __restrict__ x,
    const int* __restrict__ esrc, const int* __restrict__ edst,
    const int* __restrict__ states, int n_states,
    const int* __restrict__ actions,
    const float* __restrict__ W1s, const float* __restrict__ W1n, const float* __restrict__ b1,
    const float* __restrict__ W2s, const float* __restrict__ W2n, const float* __restrict__ b2,
    const float* __restrict__ Wfc, const float* __restrict__ bfc,
    float* __restrict__ out)
{
    __shared__ Smem sm;
    int tid = threadIdx.x;

    // ---- P0: init (block 0 only): zero bitmaps+counters, insert seeds ----
    if (blockIdx.x == 0) {
        for (int i = tid; i < BM_WORDS; i += BS) { g_bm1[i] = 0u; g_bm2[i] = 0u; }
        if (tid == 0) { g_n1 = 0; g_n2 = 0; g_ne1 = 0; g_ne2 = 0; }
        __syncthreads();
        for (int t = tid; t <= n_states; t += BS) {
            int node = (t < n_states) ? states[t] : actions[0];
            unsigned bit = 1u << (node & 31);
            unsigned old2 = atomicOr(&g_bm2[node >> 5], bit);
            if (!(old2 & bit)) {
                int p = atomicAdd(&g_n2, 1);
                g_list2[p] = node;
                g_deg2[node] = 0;
            }
            unsigned old1 = atomicOr(&g_bm1[node >> 5], bit);
            if (!(old1 & bit)) {
                int p = atomicAdd(&g_n1, 1);
                g_list1[p] = node;
                g_deg1[node] = 0;
            }
        }
    }
    grid_barrier();

    // ---- P1: zero agg2(list2); passA (edges into S2 -> elist2, srcs -> S1) ----
    zero_phase(g_list2, g_n2, g_agg2);
    pass_phase(&sm, esrc, edst, g_bm2, g_elist2, &g_ne2, g_deg2, true);
    grid_barrier();

    // ---- P2: zero agg1(list1); passB (edges into S1 -> elist1) ----
    zero_phase(g_list1, g_n1, g_agg1);
    pass_phase(&sm, esrc, edst, g_bm1, g_elist1, &g_ne1, g_deg1, false);
    grid_barrier();

    // ---- P3: layer-1 aggregation ----
    agg_phase(g_elist1, g_ne1, x, g_agg1);
    grid_barrier();

    // ---- P4: layer-1 GEMM ----
    {
        int n1 = g_n1;
        int ntiles = (n1 + 31) / 32;
        for (int t = blockIdx.x; t < ntiles; t += (int)gridDim.x)
            gemm_tile(&sm, t * 32, n1, g_list1, x, g_agg1, g_deg1, W1s, W1n, b1, g_h1);
    }
    grid_barrier();

    // ---- P5: layer-2 aggregation ----
    agg_phase(g_elist2, g_ne2, g_h1, g_agg2);
    grid_barrier();

    // ---- P6: layer-2 GEMM ----
    {
        int n2 = g_n2;
        int ntiles = (n2 + 31) / 32;
        for (int t = blockIdx.x; t < ntiles; t += (int)gridDim.x)
            gemm_tile(&sm, t * 32, n2, g_list2, g_h1, g_agg2, g_deg2, W2s, W2n, b2, g_h2);
    }
    grid_barrier();

    // ---- P7: readout (block 0 only) ----
    if (blockIdx.x == 0) {
        int f = tid;  // 128 threads
        float m = -1e30f;
#pragma unroll 4
        for (int s = 0; s < n_states; s++)
            m = fmaxf(m, g_h2[states[s] * F + f]);
        float av = g_h2[actions[0] * F + f];
        float p = m * Wfc[f] + av * Wfc[F + f];
        sm.red[f] = p;
        __syncthreads();
        for (int d = 64; d > 0; d >>= 1) {
            if (f < d) sm.red[f] += sm.red[f + d];
            __syncthreads();
        }
        if (f == 0) out[0] = sm.red[0] + bfc[0];
    }
}

// ---------------- launch ----------------
extern "C" void kernel_launch(void* const* d_in, const int* in_sizes, int n_in,
                              void* d_out, int out_size) {
    const float* x      = (const float*)d_in[0];
    const int*   esrc   = (const int*)d_in[1];
    const int*   edst   = (const int*)d_in[2];
    const int*   states = (const int*)d_in[3];
    const int*   actions= (const int*)d_in[4];
    const float* W1s    = (const float*)d_in[5];
    const float* W1n    = (const float*)d_in[6];
    const float* b1     = (const float*)d_in[7];
    const float* W2s    = (const float*)d_in[8];
    const float* W2n    = (const float*)d_in[9];
    const float* b2     = (const float*)d_in[10];
    const float* Wfc    = (const float*)d_in[11];
    const float* bfc    = (const float*)d_in[12];
    float* out = (float*)d_out;
    int n_states = in_sizes[3];

    mega_kernel<<<NB, BS>>>(x, esrc, edst, states, n_states, actions,
                            W1s, W1n, b1, W2s, W2n, b2, Wfc, bfc, out);
}

// round 10
// speedup vs baseline: 1.1289x; 1.1289x over previous
#include <cuda_runtime.h>

#define N_NODES 50000
#define N_EDGES 800000
#define QUADS   (N_EDGES / 4)
#define F 128
#define BM_WORDS ((N_NODES + 31) / 32)

#define NB1 740      // K1 grid: 5 blocks/SM x 148
#define BS1 256
#define NB2 592      // K2 grid: 4 blocks/SM x 148
#define BS2 128

// ---- scratch (static device arrays; no allocation allowed) ----
__device__ unsigned g_bm1[BM_WORDS];
__device__ unsigned g_bm2[BM_WORDS];
__device__ int   g_list1[N_NODES];
__device__ int   g_list2[512];
__device__ int   g_deg1[N_NODES];
__device__ int   g_deg2[N_NODES];
__device__ int2  g_elist1[N_EDGES];
__device__ int2  g_elist2[N_EDGES];
__device__ int   g_n1, g_n2, g_ne1, g_ne2;
__device__ float g_agg1[N_NODES * F];
__device__ float g_agg2[N_NODES * F];
__device__ float g_h1[N_NODES * F];
__device__ float g_h2[N_NODES * F];

// ---- device-wide barrier state (zero-initialized; gen persists across launches) ----
__device__ int      g_bar_arrive;
__device__ unsigned g_bar_gen;

__device__ __forceinline__ bool bm_test(const unsigned* bm, int n) {
    return (bm[n >> 5] >> (n & 31)) & 1u;
}

// Sense-reversing grid barrier (all blocks must be resident).
__device__ __forceinline__ void grid_barrier() {
    __syncthreads();
    if (threadIdx.x == 0) {
        __threadfence();
        unsigned gen = atomicAdd(&g_bar_gen, 0u);
        if (atomicAdd(&g_bar_arrive, 1) == (int)gridDim.x - 1) {
            g_bar_arrive = 0;
            __threadfence();
            atomicAdd(&g_bar_gen, 1u);
        } else {
            while (atomicAdd(&g_bar_gen, 0u) == gen)
                __nanosleep(128);
        }
        __threadfence();
    }
    __syncthreads();
}

// ---------------- edge filter phase (hierarchical compaction, PROVEN body) ----
__device__ void pass_phase(int* s_cnt, int* s_base,
                           const int* __restrict__ src, const int* __restrict__ dst,
                           const unsigned* __restrict__ bm,
                           int2* __restrict__ elist, int* __restrict__ ne,
                           int* __restrict__ deg, bool expand) {
    int tid  = threadIdx.x;
    int lane = tid & 31;
    int bs   = blockDim.x;
    for (int base = blockIdx.x * bs; base < QUADS; base += (int)gridDim.x * bs) {
        if (tid == 0) *s_cnt = 0;
        __syncthreads();

        int i4 = base + tid;
        bool valid = (i4 < QUADS);
        int4 d4 = valid ? ((const int4*)dst)[i4] : make_int4(0, 0, 0, 0);
        int4 s4 = valid ? ((const int4*)src)[i4] : make_int4(0, 0, 0, 0);
        int dv[4] = {d4.x, d4.y, d4.z, d4.w};
        int sv[4] = {s4.x, s4.y, s4.z, s4.w};
        bool pass[4];
        int my = 0;
#pragma unroll
        for (int j = 0; j < 4; j++) {
            pass[j] = valid && bm_test(bm, dv[j]);
            my += pass[j] ? 1 : 0;
        }
        int scan = my;
#pragma unroll
        for (int d = 1; d < 32; d <<= 1) {
            int t = __shfl_up_sync(0xffffffff, scan, d);
            if (lane >= d) scan += t;
        }
        int wtotal = __shfl_sync(0xffffffff, scan, 31);
        int wbase = 0;
        if (lane == 31 && wtotal > 0) wbase = atomicAdd(s_cnt, wtotal);
        wbase = __shfl_sync(0xffffffff, wbase, 31);
        int my_off = wbase + scan - my;
        __syncthreads();
        if (tid == 0) *s_base = (*s_cnt > 0) ? atomicAdd(ne, *s_cnt) : 0;
        __syncthreads();
        int p = *s_base + my_off;
#pragma unroll
        for (int j = 0; j < 4; j++) {
            if (pass[j]) {
                elist[p++] = make_int2(sv[j], dv[j]);
                atomicAdd(&deg[dv[j]], 1);
                if (expand) {
                    unsigned bit = 1u << (sv[j] & 31);
                    unsigned old = atomicOr(&g_bm1[sv[j] >> 5], bit);
                    if (!(old & bit)) {
                        int q = atomicAdd(&g_n1, 1);
                        g_list1[q] = sv[j];
                        g_deg1[sv[j]] = 0;
                    }
                }
            }
        }
        __syncthreads();
    }
}

// ---------------- zero agg rows for listed nodes (warp per node) ---------------
__device__ void zero_phase(const int* __restrict__ list, int count, float* __restrict__ agg) {
    int gw   = (blockIdx.x * blockDim.x + threadIdx.x) >> 5;
    int nw   = ((int)gridDim.x * blockDim.x) >> 5;
    int lane = threadIdx.x & 31;
    for (int w = gw; w < count; w += nw)
        ((float4*)agg)[list[w] * 32 + lane] = make_float4(0.f, 0.f, 0.f, 0.f);
}

// ---------------- edge aggregation: warp per edge, vector red (PROVEN) ---------
__device__ void agg_phase(const int2* __restrict__ elist, int ne,
                          const float* __restrict__ feat, float* __restrict__ agg) {
    int gw   = (blockIdx.x * blockDim.x + threadIdx.x) >> 5;
    int nw   = ((int)gridDim.x * blockDim.x) >> 5;
    int lane = threadIdx.x & 31;
    for (int j = gw; j < ne; j += nw) {
        int2 e = elist[j];
        float4 v = ((const float4*)feat)[e.x * 32 + lane];
        float* a = &agg[e.y * F + lane * 4];
        asm volatile("red.global.add.v4.f32 [%0], {%1, %2, %3, %4};"
                     :: "l"(a), "f"(v.x), "f"(v.y), "f"(v.z), "f"(v.w) : "memory");
    }
}

// ================= K1: frontier + layer-1 aggregation (high occupancy) =========
__global__ void __launch_bounds__(BS1, 5) frontier_kernel(
    const int* __restrict__ esrc, const int* __restrict__ edst,
    const int* __restrict__ states, int n_states,
    const int* __restrict__ actions,
    const float* __restrict__ x)
{
    __shared__ int s_cnt, s_base;
    int tid = threadIdx.x;

    // ---- P0: init ----
    {
        int g = blockIdx.x * BS1 + tid;
        int n = (int)gridDim.x * BS1;
        for (int i = g; i < BM_WORDS; i += n) { g_bm1[i] = 0u; g_bm2[i] = 0u; }
        if (g == 0) { g_n1 = 0; g_n2 = 0; g_ne1 = 0; g_ne2 = 0; }
    }
    grid_barrier();
    if (blockIdx.x == 0) {
        for (int t = tid; t <= n_states; t += BS1) {
            int node = (t < n_states) ? states[t] : actions[0];
            unsigned bit = 1u << (node & 31);
            unsigned old2 = atomicOr(&g_bm2[node >> 5], bit);
            if (!(old2 & bit)) {
                int p = atomicAdd(&g_n2, 1);
                g_list2[p] = node;
                g_deg2[node] = 0;
            }
            unsigned old1 = atomicOr(&g_bm1[node >> 5], bit);
            if (!(old1 & bit)) {
                int p = atomicAdd(&g_n1, 1);
                g_list1[p] = node;
                g_deg1[node] = 0;
            }
        }
    }
    grid_barrier();

    // ---- P1: zero agg2(list2); passA (edges into S2 -> elist2, srcs -> S1) ----
    zero_phase(g_list2, g_n2, g_agg2);
    pass_phase(&s_cnt, &s_base, esrc, edst, g_bm2, g_elist2, &g_ne2, g_deg2, true);
    grid_barrier();

    // ---- P2: zero agg1(list1); passB (edges into S1 -> elist1) ----
    zero_phase(g_list1, g_n1, g_agg1);
    pass_phase(&s_cnt, &s_base, esrc, edst, g_bm1, g_elist1, &g_ne1, g_deg1, false);
    grid_barrier();

    // ---- P3: layer-1 aggregation ----
    agg_phase(g_elist1, g_ne1, x, g_agg1);
}

// ---------------- fused SAGE GEMM tile (PROVEN 128-thread 4x8 body) ------------
struct GemmSmem {
    int   rows[32];
    float invs[32];
    float As[32][36];
    float Bs[32][132];
};

__device__ void gemm_tile(GemmSmem* sm, int m0, int count,
                          const int* __restrict__ list,
                          const float* __restrict__ feat, const float* __restrict__ agg,
                          const int* __restrict__ deg,
                          const float* __restrict__ Ws, const float* __restrict__ Wn,
                          const float* __restrict__ bias, float* __restrict__ outp) {
    int tid = threadIdx.x;
    int r0  = (tid >> 4) * 4;
    int c0  = (tid & 15) * 8;

    if (tid < 32) {
        int nd = (m0 + tid < count) ? list[m0 + tid] : -1;
        sm->rows[tid] = nd;
        sm->invs[tid] = (nd >= 0) ? 1.0f / (float)max(deg[nd], 1) : 0.f;
    }
    __syncthreads();

    float acc[4][8];
#pragma unroll
    for (int m = 0; m < 4; m++)
#pragma unroll
        for (int n = 0; n < 8; n++) acc[m][n] = 0.f;

#pragma unroll 1
    for (int kt = 0; kt < 8; kt++) {
        const float* A = (kt < 4) ? feat : agg;
        const float* W = (kt < 4) ? Ws : Wn;
        int kb4 = (kt & 3) * 8;

#pragma unroll
        for (int i = 0; i < 2; i++) {
            int v   = tid + 128 * i;
            int row = v >> 3;
            int kq  = v & 7;
            int nd  = sm->rows[row];
            float4 a = make_float4(0.f, 0.f, 0.f, 0.f);
            if (nd >= 0) a = ((const float4*)A)[nd * 32 + kb4 + kq];
            float sc = (kt < 4) ? 1.0f : sm->invs[row];
            sm->As[kq * 4 + 0][row] = a.x * sc;
            sm->As[kq * 4 + 1][row] = a.y * sc;
            sm->As[kq * 4 + 2][row] = a.z * sc;
            sm->As[kq * 4 + 3][row] = a.w * sc;
        }
#pragma unroll
        for (int i = 0; i < 8; i++) {
            int v  = tid + 128 * i;
            int c  = v >> 3;
            int kq = v & 7;
            float4 w = ((const float4*)W)[c * 32 + kb4 + kq];
            sm->Bs[kq * 4 + 0][c] = w.x;
            sm->Bs[kq * 4 + 1][c] = w.y;
            sm->Bs[kq * 4 + 2][c] = w.z;
            sm->Bs[kq * 4 + 3][c] = w.w;
        }
        __syncthreads();

#pragma unroll
        for (int k = 0; k < 32; k++) {
            float4 a4 = *(const float4*)&sm->As[k][r0];
            float4 b0 = *(const float4*)&sm->Bs[k][c0];
            float4 b1 = *(const float4*)&sm->Bs[k][c0 + 4];
            float am[4] = {a4.x, a4.y, a4.z, a4.w};
            float bn[8] = {b0.x, b0.y, b0.z, b0.w, b1.x, b1.y, b1.z, b1.w};
#pragma unroll
            for (int m = 0; m < 4; m++)
#pragma unroll
                for (int n = 0; n < 8; n++)
                    acc[m][n] += am[m] * bn[n];
        }
        __syncthreads();
    }

    float bv[8];
#pragma unroll
    for (int n = 0; n < 8; n++) bv[n] = bias[c0 + n];

#pragma unroll
    for (int m = 0; m < 4; m++) {
        int nd = sm->rows[r0 + m];
        if (nd >= 0) {
            float4 o0, o1;
            o0.x = fmaxf(acc[m][0] + bv[0], 0.f);
            o0.y = fmaxf(acc[m][1] + bv[1], 0.f);
            o0.z = fmaxf(acc[m][2] + bv[2], 0.f);
            o0.w = fmaxf(acc[m][3] + bv[3], 0.f);
            o1.x = fmaxf(acc[m][4] + bv[4], 0.f);
            o1.y = fmaxf(acc[m][5] + bv[5], 0.f);
            o1.z = fmaxf(acc[m][6] + bv[6], 0.f);
            o1.w = fmaxf(acc[m][7] + bv[7], 0.f);
            ((float4*)outp)[nd * 32 + (c0 >> 2)]     = o0;
            ((float4*)outp)[nd * 32 + (c0 >> 2) + 1] = o1;
        }
    }
    __syncthreads();
}

// ================= K2: GEMMs + layer-2 agg + readout ==========================
__global__ void __launch_bounds__(BS2, 4) compute_kernel(
    const float* __restrict__ x,
    const int* __restrict__ states, int n_states,
    const int* __restrict__ actions,
    const float* __restrict__ W1s, const float* __restrict__ W1n, const float* __restrict__ b1,
    const float* __restrict__ W2s, const float* __restrict__ W2n, const float* __restrict__ b2,
    const float* __restrict__ Wfc, const float* __restrict__ bfc,
    float* __restrict__ out)
{
    __shared__ GemmSmem sm;
    int tid = threadIdx.x;

    // ---- P4: layer-1 GEMM ----
    {
        int n1 = g_n1;
        int ntiles = (n1 + 31) / 32;
        for (int t = blockIdx.x; t < ntiles; t += (int)gridDim.x)
            gemm_tile(&sm, t * 32, n1, g_list1, x, g_agg1, g_deg1, W1s, W1n, b1, g_h1);
    }
    grid_barrier();

    // ---- P5: layer-2 aggregation ----
    agg_phase(g_elist2, g_ne2, g_h1, g_agg2);
    grid_barrier();

    // ---- P6: layer-2 GEMM ----
    {
        int n2 = g_n2;
        int ntiles = (n2 + 31) / 32;
        for (int t = blockIdx.x; t < ntiles; t += (int)gridDim.x)
            gemm_tile(&sm, t * 32, n2, g_list2, g_h1, g_agg2, g_deg2, W2s, W2n, b2, g_h2);
    }
    grid_barrier();

    // ---- P7: readout (block 0 only) ----
    if (blockIdx.x == 0) {
        int f = tid;  // 128 threads
        float m = -1e30f;
#pragma unroll 4
        for (int s = 0; s < n_states; s++)
            m = fmaxf(m, g_h2[states[s] * F + f]);
        float av = g_h2[actions[0] * F + f];
        float p = m * Wfc[f] + av * Wfc[F + f];
        float* red = (float*)&sm;           // reuse smem
        red[f] = p;
        __syncthreads();
        for (int d = 64; d > 0; d >>= 1) {
            if (f < d) red[f] += red[f + d];
            __syncthreads();
        }
        if (f == 0) out[0] = red[0] + bfc[0];
    }
}

// ---------------- launch ----------------
extern "C" void kernel_launch(void* const* d_in, const int* in_sizes, int n_in,
                              void* d_out, int out_size) {
    const float* x      = (const float*)d_in[0];
    const int*   esrc   = (const int*)d_in[1];
    const int*   edst   = (const int*)d_in[2];
    const int*   states = (const int*)d_in[3];
    const int*   actions= (const int*)d_in[4];
    const float* W1s    = (const float*)d_in[5];
    const float* W1n    = (const float*)d_in[6];
    const float* b1     = (const float*)d_in[7];
    const float* W2s    = (const float*)d_in[8];
    const float* W2n    = (const float*)d_in[9];
    const float* b2     = (const float*)d_in[10];
    const float* Wfc    = (const float*)d_in[11];
    const float* bfc    = (const float*)d_in[12];
    float* out = (float*)d_out;
    int n_states = in_sizes[3];

    frontier_kernel<<<NB1, BS1>>>(esrc, edst, states, n_states, actions, x);
    compute_kernel<<<NB2, BS2>>>(x, states, n_states, actions,
                                 W1s, W1n, b1, W2s, W2n, b2, Wfc, bfc, out);
}

// round 11
// speedup vs baseline: 1.1759x; 1.0416x over previous
#include <cuda_runtime.h>

#define N_NODES 50000
#define N_EDGES 800000
#define QUADS   (N_EDGES / 4)
#define F 128
#define BM_WORDS ((N_NODES + 31) / 32)

#define NB 592       // 4 blocks/SM x 148 SMs
#define BS 256

// ---- scratch (static device arrays; no allocation allowed) ----
__device__ unsigned g_bm1[BM_WORDS];
__device__ unsigned g_bm2[BM_WORDS];
__device__ int   g_list1[N_NODES];
__device__ int   g_list2[512];
__device__ int   g_deg1[N_NODES];
__device__ int   g_deg2[N_NODES];
__device__ int2  g_elist1[N_EDGES];
__device__ int2  g_elist2[N_EDGES];
__device__ int   g_n1, g_n2, g_ne1, g_ne2;
__device__ float g_agg1[N_NODES * F];
__device__ float g_agg2[N_NODES * F];
__device__ float g_h1[N_NODES * F];
__device__ float g_h2[N_NODES * F];
__device__ int   g_smax[F];          // states-max bits (floats >= 0)

// ---- device-wide barrier state (zero-initialized; gen persists across replays) ----
__device__ int      g_bar_arrive;
__device__ unsigned g_bar_gen;

__device__ __forceinline__ bool bm_test(const unsigned* bm, int n) {
    return (bm[n >> 5] >> (n & 31)) & 1u;
}

// Sense-reversing grid barrier (all blocks resident by construction).
__device__ __forceinline__ void grid_barrier() {
    __syncthreads();
    if (threadIdx.x == 0) {
        __threadfence();
        unsigned gen = *(volatile unsigned*)&g_bar_gen;
        if (atomicAdd(&g_bar_arrive, 1) == (int)gridDim.x - 1) {
            g_bar_arrive = 0;
            __threadfence();
            atomicAdd(&g_bar_gen, 1u);
        } else {
            while (*(volatile unsigned*)&g_bar_gen == gen)
                __nanosleep(128);
        }
        __threadfence();
    }
    __syncthreads();
}

// ---------------- edge filter phase (hierarchical compaction, PROVEN body) ----
__device__ void pass_phase(int* s_cnt, int* s_base,
                           const int* __restrict__ src, const int* __restrict__ dst,
                           const unsigned* __restrict__ bm,
                           int2* __restrict__ elist, int* __restrict__ ne,
                           int* __restrict__ deg, bool expand) {
    int tid  = threadIdx.x;
    int lane = tid & 31;
    for (int base = blockIdx.x * BS; base < QUADS; base += NB * BS) {
        if (tid == 0) *s_cnt = 0;
        __syncthreads();

        int i4 = base + tid;
        bool valid = (i4 < QUADS);
        int4 d4 = valid ? ((const int4*)dst)[i4] : make_int4(0, 0, 0, 0);
        int4 s4 = valid ? ((const int4*)src)[i4] : make_int4(0, 0, 0, 0);
        int dv[4] = {d4.x, d4.y, d4.z, d4.w};
        int sv[4] = {s4.x, s4.y, s4.z, s4.w};
        bool pass[4];
        int my = 0;
#pragma unroll
        for (int j = 0; j < 4; j++) {
            pass[j] = valid && bm_test(bm, dv[j]);
            my += pass[j] ? 1 : 0;
        }
        int scan = my;
#pragma unroll
        for (int d = 1; d < 32; d <<= 1) {
            int t = __shfl_up_sync(0xffffffff, scan, d);
            if (lane >= d) scan += t;
        }
        int wtotal = __shfl_sync(0xffffffff, scan, 31);
        int wbase = 0;
        if (lane == 31 && wtotal > 0) wbase = atomicAdd(s_cnt, wtotal);
        wbase = __shfl_sync(0xffffffff, wbase, 31);
        int my_off = wbase + scan - my;
        __syncthreads();
        if (tid == 0) *s_base = (*s_cnt > 0) ? atomicAdd(ne, *s_cnt) : 0;
        __syncthreads();
        int p = *s_base + my_off;
#pragma unroll
        for (int j = 0; j < 4; j++) {
            if (pass[j]) {
                elist[p++] = make_int2(sv[j], dv[j]);
                atomicAdd(&deg[dv[j]], 1);
                if (expand) {
                    unsigned bit = 1u << (sv[j] & 31);
                    unsigned old = atomicOr(&g_bm1[sv[j] >> 5], bit);
                    if (!(old & bit)) {
                        int q = atomicAdd(&g_n1, 1);
                        g_list1[q] = sv[j];
                        g_deg1[sv[j]] = 0;
                    }
                }
            }
        }
        __syncthreads();
    }
}

// ---------------- zero agg rows for listed nodes (warp per node) ---------------
__device__ void zero_phase(const int* __restrict__ list, int count, float* __restrict__ agg) {
    int gw   = (blockIdx.x * BS + threadIdx.x) >> 5;
    int nw   = (NB * BS) >> 5;
    int lane = threadIdx.x & 31;
    for (int w = gw; w < count; w += nw)
        ((float4*)agg)[list[w] * 32 + lane] = make_float4(0.f, 0.f, 0.f, 0.f);
}

// ---------------- edge aggregation: warp per edge, vector red (PROVEN) ---------
__device__ void agg_phase(const int2* __restrict__ elist, int ne,
                          const float* __restrict__ feat, float* __restrict__ agg) {
    int gw   = (blockIdx.x * BS + threadIdx.x) >> 5;
    int nw   = (NB * BS) >> 5;
    int lane = threadIdx.x & 31;
    for (int j = gw; j < ne; j += nw) {
        int2 e = elist[j];
        float4 v = ((const float4*)feat)[e.x * 32 + lane];
        float* a = &agg[e.y * F + lane * 4];
        asm volatile("red.global.add.v4.f32 [%0], {%1, %2, %3, %4};"
                     :: "l"(a), "f"(v.x), "f"(v.y), "f"(v.z), "f"(v.w) : "memory");
    }
}

// ---------------- fused SAGE GEMM tile (256 threads, 2x8 outputs/thread) -------
struct GemmSmem {
    int   rows[32];
    float invs[32];
    float As[32][36];
    float Bs[32][132];
};

__device__ void gemm_tile(GemmSmem* sm, int m0, int count,
                          const int* __restrict__ list,
                          const float* __restrict__ feat, const float* __restrict__ agg,
                          const int* __restrict__ deg,
                          const float* __restrict__ Ws, const float* __restrict__ Wn,
                          const float* __restrict__ bias, float* __restrict__ outp) {
    int tid = threadIdx.x;
    int r0  = (tid >> 4) * 2;     // 0..30 step 2
    int c0  = (tid & 15) * 8;     // 0..120 step 8

    if (tid < 32) {
        int nd = (m0 + tid < count) ? list[m0 + tid] : -1;
        sm->rows[tid] = nd;
        sm->invs[tid] = (nd >= 0) ? 1.0f / (float)max(deg[nd], 1) : 0.f;
    }
    __syncthreads();

    float acc[2][8];
#pragma unroll
    for (int m = 0; m < 2; m++)
#pragma unroll
        for (int n = 0; n < 8; n++) acc[m][n] = 0.f;

#pragma unroll 1
    for (int kt = 0; kt < 8; kt++) {
        const float* A = (kt < 4) ? feat : agg;
        const float* W = (kt < 4) ? Ws : Wn;
        int kb4 = (kt & 3) * 8;

        // A tile: 32 rows x 32 k = 256 float4, 1 per thread
        {
            int row = tid >> 3;
            int kq  = tid & 7;
            int nd  = sm->rows[row];
            float4 a = make_float4(0.f, 0.f, 0.f, 0.f);
            if (nd >= 0) a = ((const float4*)A)[nd * 32 + kb4 + kq];
            float sc = (kt < 4) ? 1.0f : sm->invs[row];
            sm->As[kq * 4 + 0][row] = a.x * sc;
            sm->As[kq * 4 + 1][row] = a.y * sc;
            sm->As[kq * 4 + 2][row] = a.z * sc;
            sm->As[kq * 4 + 3][row] = a.w * sc;
        }
        // W tile: 128 cols x 32 k = 1024 float4, 4 per thread
#pragma unroll
        for (int i = 0; i < 4; i++) {
            int v  = tid + 256 * i;
            int c  = v >> 3;
            int kq = v & 7;
            float4 w = ((const float4*)W)[c * 32 + kb4 + kq];
            sm->Bs[kq * 4 + 0][c] = w.x;
            sm->Bs[kq * 4 + 1][c] = w.y;
            sm->Bs[kq * 4 + 2][c] = w.z;
            sm->Bs[kq * 4 + 3][c] = w.w;
        }
        __syncthreads();

#pragma unroll
        for (int k = 0; k < 32; k++) {
            float2 a2 = *(const float2*)&sm->As[k][r0];
            float4 b0 = *(const float4*)&sm->Bs[k][c0];
            float4 b1 = *(const float4*)&sm->Bs[k][c0 + 4];
            float am[2] = {a2.x, a2.y};
            float bn[8] = {b0.x, b0.y, b0.z, b0.w, b1.x, b1.y, b1.z, b1.w};
#pragma unroll
            for (int m = 0; m < 2; m++)
#pragma unroll
                for (int n = 0; n < 8; n++)
                    acc[m][n] += am[m] * bn[n];
        }
        __syncthreads();
    }

    float bv[8];
#pragma unroll
    for (int n = 0; n < 8; n++) bv[n] = bias[c0 + n];

#pragma unroll
    for (int m = 0; m < 2; m++) {
        int nd = sm->rows[r0 + m];
        if (nd >= 0) {
            float4 o0, o1;
            o0.x = fmaxf(acc[m][0] + bv[0], 0.f);
            o0.y = fmaxf(acc[m][1] + bv[1], 0.f);
            o0.z = fmaxf(acc[m][2] + bv[2], 0.f);
            o0.w = fmaxf(acc[m][3] + bv[3], 0.f);
            o1.x = fmaxf(acc[m][4] + bv[4], 0.f);
            o1.y = fmaxf(acc[m][5] + bv[5], 0.f);
            o1.z = fmaxf(acc[m][6] + bv[6], 0.f);
            o1.w = fmaxf(acc[m][7] + bv[7], 0.f);
            ((float4*)outp)[nd * 32 + (c0 >> 2)]     = o0;
            ((float4*)outp)[nd * 32 + (c0 >> 2) + 1] = o1;
        }
    }
    __syncthreads();
}

// ================= the fused kernel ==========================================
__global__ void __launch_bounds__(BS, 4) mega_kernel(
    const float* __restrict__ x,
    const int* __restrict__ esrc, const int* __restrict__ edst,
    const int* __restrict__ states, int n_states,
    const int* __restrict__ actions,
    const float* __restrict__ W1s, const float* __restrict__ W1n, const float* __restrict__ b1,
    const float* __restrict__ W2s, const float* __restrict__ W2n, const float* __restrict__ b2,
    const float* __restrict__ Wfc, const float* __restrict__ bfc,
    float* __restrict__ out)
{
    __shared__ GemmSmem sm;
    __shared__ int s_cnt, s_base;
    int tid = threadIdx.x;

    // ---- P0a: zero bitmaps, counters, smax (grid-wide) ----
    {
        int g = blockIdx.x * BS + tid;
        int n = NB * BS;
        for (int i = g; i < BM_WORDS; i += n) { g_bm1[i] = 0u; g_bm2[i] = 0u; }
        if (g < F) g_smax[g] = 0;
        if (g == 0) { g_n1 = 0; g_n2 = 0; g_ne1 = 0; g_ne2 = 0; }
    }
    grid_barrier();

    // ---- P0b: seed S2 (and S1) from states+action (block 0) ----
    if (blockIdx.x == 0) {
        for (int t = tid; t <= n_states; t += BS) {
            int node = (t < n_states) ? states[t] : actions[0];
            unsigned bit = 1u << (node & 31);
            unsigned old2 = atomicOr(&g_bm2[node >> 5], bit);
            if (!(old2 & bit)) {
                int p = atomicAdd(&g_n2, 1);
                g_list2[p] = node;
                g_deg2[node] = 0;
            }
            unsigned old1 = atomicOr(&g_bm1[node >> 5], bit);
            if (!(old1 & bit)) {
                int p = atomicAdd(&g_n1, 1);
                g_list1[p] = node;
                g_deg1[node] = 0;
            }
        }
    }
    grid_barrier();

    // ---- P1: zero agg2(list2); passA ----
    zero_phase(g_list2, g_n2, g_agg2);
    pass_phase(&s_cnt, &s_base, esrc, edst, g_bm2, g_elist2, &g_ne2, g_deg2, true);
    grid_barrier();

    // ---- P2: zero agg1(list1); passB ----
    zero_phase(g_list1, g_n1, g_agg1);
    pass_phase(&s_cnt, &s_base, esrc, edst, g_bm1, g_elist1, &g_ne1, g_deg1, false);
    grid_barrier();

    // ---- P3: layer-1 aggregation ----
    agg_phase(g_elist1, g_ne1, x, g_agg1);
    grid_barrier();

    // ---- P4: layer-1 GEMM ----
    {
        int n1 = g_n1;
        int ntiles = (n1 + 31) / 32;
        for (int t = blockIdx.x; t < ntiles; t += NB)
            gemm_tile(&sm, t * 32, n1, g_list1, x, g_agg1, g_deg1, W1s, W1n, b1, g_h1);
    }
    grid_barrier();

    // ---- P5: layer-2 aggregation ----
    agg_phase(g_elist2, g_ne2, g_h1, g_agg2);
    grid_barrier();

    // ---- P6: layer-2 GEMM ----
    {
        int n2 = g_n2;
        int ntiles = (n2 + 31) / 32;
        for (int t = blockIdx.x; t < ntiles; t += NB)
            gemm_tile(&sm, t * 32, n2, g_list2, g_h1, g_agg2, g_deg2, W2s, W2n, b2, g_h2);
    }
    grid_barrier();

    // ---- P7a: parallel states-max (one warp per state row; int atomicMax, vals>=0) --
    {
        int gw   = (blockIdx.x * BS + tid) >> 5;
        int nw   = (NB * BS) >> 5;
        int lane = tid & 31;
        for (int s = gw; s < n_states; s += nw) {
            float4 v = ((const float4*)g_h2)[states[s] * 32 + lane];
            atomicMax(&g_smax[lane * 4 + 0], __float_as_int(v.x));
            atomicMax(&g_smax[lane * 4 + 1], __float_as_int(v.y));
            atomicMax(&g_smax[lane * 4 + 2], __float_as_int(v.z));
            atomicMax(&g_smax[lane * 4 + 3], __float_as_int(v.w));
        }
    }
    grid_barrier();

    // ---- P7b: final dot (block 0) ----
    if (blockIdx.x == 0) {
        float p = 0.f;
        if (tid < F) {
            float m  = __int_as_float(g_smax[tid]);
            float av = g_h2[actions[0] * F + tid];
            p = m * Wfc[tid] + av * Wfc[F + tid];
        }
        float* red = (float*)&sm;
        red[tid] = p;
        __syncthreads();
        for (int d = 128; d > 0; d >>= 1) {
            if (tid < d) red[tid] += red[tid + d];
            __syncthreads();
        }
        if (tid == 0) out[0] = red[0] + bfc[0];
    }
}

// ---------------- launch ----------------
extern "C" void kernel_launch(void* const* d_in, const int* in_sizes, int n_in,
                              void* d_out, int out_size) {
    const float* x      = (const float*)d_in[0];
    const int*   esrc   = (const int*)d_in[1];
    const int*   edst   = (const int*)d_in[2];
    const int*   states = (const int*)d_in[3];
    const int*   actions= (const int*)d_in[4];
    const float* W1s    = (const float*)d_in[5];
    const float* W1n    = (const float*)d_in[6];
    const float* b1     = (const float*)d_in[7];
    const float* W2s    = (const float*)d_in[8];
    const float* W2n    = (const float*)d_in[9];
    const float* b2     = (const float*)d_in[10];
    const float* Wfc    = (const float*)d_in[11];
    const float* bfc    = (const float*)d_in[12];
    float* out = (float*)d_out;
    int n_states = in_sizes[3];

    mega_kernel<<<NB, BS>>>(x, esrc, edst, states, n_states, actions,
                            W1s, W1n, b1, W2s, W2n, b2, Wfc, bfc, out);
}

// round 12
// speedup vs baseline: 1.6169x; 1.3750x over previous
#include <cuda_runtime.h>

#define N_NODES 50000
#define N_EDGES 800000
#define QUADS   (N_EDGES / 4)
#define F 128
#define BM_WORDS ((N_NODES + 31) / 32)

// ---- scratch (static device arrays; zero-initialized; no allocation allowed) ----
__device__ unsigned g_bm1[BM_WORDS];
__device__ unsigned g_bm2[BM_WORDS];
__device__ int   g_list1[N_NODES];
__device__ int   g_list2[512];
__device__ int   g_deg1[N_NODES];
__device__ int   g_deg2[N_NODES];
__device__ int2  g_elist2[N_EDGES];
__device__ int   g_n1, g_n2, g_ne2;
__device__ float g_agg1[N_NODES * F];   // invariant: zero at call entry (gemm1 re-zeroes)
__device__ float g_agg2[N_NODES * F];   // invariant: zero at call entry (gemm2 re-zeroes)
__device__ float g_h1[N_NODES * F];
__device__ float g_h2[N_NODES * F];

__device__ __forceinline__ bool bm_test(const unsigned* bm, int n) {
    return (bm[n >> 5] >> (n & 31)) & 1u;
}

// ---------------- init: zero bitmaps+counters, insert S2 seeds (1 block) -------
__global__ void __launch_bounds__(512) init_kernel(const int* __restrict__ states,
                                                   int n_states,
                                                   const int* __restrict__ actions) {
    int tid = threadIdx.x;
    for (int i = tid; i < BM_WORDS; i += 512) { g_bm1[i] = 0u; g_bm2[i] = 0u; }
    if (tid == 0) { g_n1 = 0; g_n2 = 0; g_ne2 = 0; }
    __syncthreads();
    for (int t = tid; t <= n_states; t += 512) {
        int node = (t < n_states) ? states[t] : actions[0];
        unsigned bit = 1u << (node & 31);
        unsigned old2 = atomicOr(&g_bm2[node >> 5], bit);
        if (!(old2 & bit)) {
            int p = atomicAdd(&g_n2, 1);
            g_list2[p] = node;
            g_deg2[node] = 0;
        }
        unsigned old1 = atomicOr(&g_bm1[node >> 5], bit);
        if (!(old1 & bit)) {
            int p = atomicAdd(&g_n1, 1);
            g_list1[p] = node;
            g_deg1[node] = 0;
        }
    }
}

// ---------------- pass A: edges into S2 -> elist2 (+deg2), sources -> S1 -------
__global__ void __launch_bounds__(256) passA_kernel(const int* __restrict__ src,
                                                    const int* __restrict__ dst) {
    __shared__ int s_cnt, s_base;
    if (threadIdx.x == 0) s_cnt = 0;
    __syncthreads();

    int i4 = blockIdx.x * blockDim.x + threadIdx.x;
    int lane = threadIdx.x & 31;
    bool valid = (i4 * 4 < N_EDGES);
    int4 d4 = valid ? ((const int4*)dst)[i4] : make_int4(0, 0, 0, 0);
    int4 s4 = valid ? ((const int4*)src)[i4] : make_int4(0, 0, 0, 0);
    int dv[4] = {d4.x, d4.y, d4.z, d4.w};
    int sv[4] = {s4.x, s4.y, s4.z, s4.w};
    bool pass[4];
    int my = 0;
#pragma unroll
    for (int j = 0; j < 4; j++) {
        pass[j] = valid && bm_test(g_bm2, dv[j]);
        my += pass[j] ? 1 : 0;
    }
    int scan = my;
#pragma unroll
    for (int d = 1; d < 32; d <<= 1) {
        int t = __shfl_up_sync(0xffffffff, scan, d);
        if (lane >= d) scan += t;
    }
    int wtotal = __shfl_sync(0xffffffff, scan, 31);
    int wbase = 0;
    if (lane == 31 && wtotal > 0) wbase = atomicAdd(&s_cnt, wtotal);
    wbase = __shfl_sync(0xffffffff, wbase, 31);
    int my_off = wbase + scan - my;
    __syncthreads();
    if (threadIdx.x == 0) s_base = (s_cnt > 0) ? atomicAdd(&g_ne2, s_cnt) : 0;
    __syncthreads();
    int p = s_base + my_off;
#pragma unroll
    for (int j = 0; j < 4; j++) {
        if (pass[j]) {
            g_elist2[p++] = make_int2(sv[j], dv[j]);
            atomicAdd(&g_deg2[dv[j]], 1);
            unsigned bit = 1u << (sv[j] & 31);
            unsigned old = atomicOr(&g_bm1[sv[j] >> 5], bit);
            if (!(old & bit)) {
                int q = atomicAdd(&g_n1, 1);
                g_list1[q] = sv[j];
                g_deg1[sv[j]] = 0;
            }
        }
    }
}

// ------- fused filter + layer-1 aggregation: ballot over bm1, warp red --------
__global__ void __launch_bounds__(256) filter_agg1_kernel(const int* __restrict__ src,
                                                          const int* __restrict__ dst,
                                                          const float* __restrict__ x) {
    int gw   = (blockIdx.x * blockDim.x + threadIdx.x) >> 5;
    int nw   = ((int)gridDim.x * blockDim.x) >> 5;
    int lane = threadIdx.x & 31;
    for (int base = gw * 32; base < N_EDGES; base += nw * 32) {
        int e = base + lane;
        int d = 0, s = 0;
        bool p = false;
        if (e < N_EDGES) {
            d = dst[e];
            p = bm_test(g_bm1, d);
        }
        unsigned mask = __ballot_sync(0xffffffff, p);
        if (p) s = src[e];
        while (mask) {
            int b = __ffs(mask) - 1;
            mask &= mask - 1;
            int ss = __shfl_sync(0xffffffff, s, b);
            int dd = __shfl_sync(0xffffffff, d, b);
            float4 v = ((const float4*)x)[ss * 32 + lane];
            float* a = &g_agg1[dd * F + lane * 4];
            asm volatile("red.global.add.v4.f32 [%0], {%1, %2, %3, %4};"
                         :: "l"(a), "f"(v.x), "f"(v.y), "f"(v.z), "f"(v.w) : "memory");
            if (lane == (unsigned)b) atomicAdd(&g_deg1[dd], 1);
        }
    }
}

// ---------------- edge aggregation for layer 2: warp per edge ------------------
__global__ void edge_agg_kernel(const int2* __restrict__ elist, const int* __restrict__ ne_p,
                                const float* __restrict__ feat, float* __restrict__ agg) {
    int ne = *ne_p;
    int nwarps = (gridDim.x * blockDim.x) >> 5;
    int warp = (blockIdx.x * blockDim.x + threadIdx.x) >> 5;
    int lane = threadIdx.x & 31;
    for (int j = warp; j < ne; j += nwarps) {
        int2 e = elist[j];
        float4 v = ((const float4*)feat)[e.x * 32 + lane];
        float* a = &agg[e.y * F + lane * 4];
        asm volatile("red.global.add.v4.f32 [%0], {%1, %2, %3, %4};"
                     :: "l"(a), "f"(v.x), "f"(v.y), "f"(v.z), "f"(v.w) : "memory");
    }
}

// ------- gathered fused SAGE GEMM (PROVEN 128-thread 4x8) + agg re-zero --------
// out[node] = relu(feat[node]@Ws^T + (agg[node]/max(deg,1))@Wn^T + b)
// Epilogue re-zeroes the consumed agg rows (maintains zero-at-entry invariant).
#define MT 32
#define KT 32

__global__ void __launch_bounds__(128) gemm_list_kernel(
    const int* __restrict__ list, const int* __restrict__ count_p,
    const float* __restrict__ feat, float* __restrict__ agg,
    const int* __restrict__ deg,
    const float* __restrict__ Ws, const float* __restrict__ Wn,
    const float* __restrict__ bias, float* __restrict__ out)
{
    int count = *count_p;
    int ntiles = (count + MT - 1) / MT;
    if (blockIdx.x >= ntiles) return;

    __shared__ int   rows[MT];
    __shared__ float invs[MT];
    __shared__ float As[KT][MT + 4];
    __shared__ float Bs[KT][128 + 4];

    int tid = threadIdx.x;
    int m0  = blockIdx.x * MT;
    int r0  = (tid >> 4) * 4;     // 0..28 step 4
    int c0  = (tid & 15) * 8;     // 0..120 step 8

    if (tid < MT) {
        int nd = (m0 + tid < count) ? list[m0 + tid] : -1;
        rows[tid] = nd;
        invs[tid] = (nd >= 0) ? 1.0f / (float)max(deg[nd], 1) : 0.f;
    }
    __syncthreads();

    float acc[4][8];
#pragma unroll
    for (int m = 0; m < 4; m++)
#pragma unroll
        for (int n = 0; n < 8; n++) acc[m][n] = 0.f;

#pragma unroll 1
    for (int kt = 0; kt < 8; kt++) {
        const float* A = (kt < 4) ? feat : agg;
        const float* W = (kt < 4) ? Ws : Wn;
        int kb4 = (kt & 3) * 8;

        // A tile: 32 rows x 32 k = 256 float4, 2 per thread (scaled if agg half)
#pragma unroll
        for (int i = 0; i < 2; i++) {
            int v   = tid + 128 * i;
            int row = v >> 3;
            int kq  = v & 7;
            int nd  = rows[row];
            float4 a = make_float4(0.f, 0.f, 0.f, 0.f);
            if (nd >= 0) a = ((const float4*)A)[nd * 32 + kb4 + kq];
            float sc = (kt < 4) ? 1.0f : invs[row];
            As[kq * 4 + 0][row] = a.x * sc;
            As[kq * 4 + 1][row] = a.y * sc;
            As[kq * 4 + 2][row] = a.z * sc;
            As[kq * 4 + 3][row] = a.w * sc;
        }
        // W tile: 128 cols x 32 k = 1024 float4, 8 per thread
#pragma unroll
        for (int i = 0; i < 8; i++) {
            int v  = tid + 128 * i;
            int c  = v >> 3;
            int kq = v & 7;
            float4 w = ((const float4*)W)[c * 32 + kb4 + kq];
            Bs[kq * 4 + 0][c] = w.x;
            Bs[kq * 4 + 1][c] = w.y;
            Bs[kq * 4 + 2][c] = w.z;
            Bs[kq * 4 + 3][c] = w.w;
        }
        __syncthreads();

#pragma unroll
        for (int k = 0; k < KT; k++) {
            float4 a4 = *(const float4*)&As[k][r0];
            float4 b0 = *(const float4*)&Bs[k][c0];
            float4 b1 = *(const float4*)&Bs[k][c0 + 4];
            float am[4] = {a4.x, a4.y, a4.z, a4.w};
            float bn[8] = {b0.x, b0.y, b0.z, b0.w, b1.x, b1.y, b1.z, b1.w};
#pragma unroll
            for (int m = 0; m < 4; m++)
#pragma unroll
                for (int n = 0; n < 8; n++)
                    acc[m][n] += am[m] * bn[n];
        }
        __syncthreads();
    }

    float bv[8];
#pragma unroll
    for (int n = 0; n < 8; n++) bv[n] = bias[c0 + n];

#pragma unroll
    for (int m = 0; m < 4; m++) {
        int nd = rows[r0 + m];
        if (nd >= 0) {
            float4 o0, o1;
            o0.x = fmaxf(acc[m][0] + bv[0], 0.f);
            o0.y = fmaxf(acc[m][1] + bv[1], 0.f);
            o0.z = fmaxf(acc[m][2] + bv[2], 0.f);
            o0.w = fmaxf(acc[m][3] + bv[3], 0.f);
            o1.x = fmaxf(acc[m][4] + bv[4], 0.f);
            o1.y = fmaxf(acc[m][5] + bv[5], 0.f);
            o1.z = fmaxf(acc[m][6] + bv[6], 0.f);
            o1.w = fmaxf(acc[m][7] + bv[7], 0.f);
            ((float4*)out)[nd * 32 + (c0 >> 2)]     = o0;
            ((float4*)out)[nd * 32 + (c0 >> 2) + 1] = o1;
        }
    }

    // epilogue: re-zero consumed agg rows (32 rows x 32 float4 = 1024, 8/thread)
#pragma unroll
    for (int i = 0; i < 8; i++) {
        int v   = tid + 128 * i;
        int row = v >> 5;
        int c   = v & 31;
        int nd  = rows[row];
        if (nd >= 0) ((float4*)agg)[nd * 32 + c] = make_float4(0.f, 0.f, 0.f, 0.f);
    }
}

// ---------------- parallel readout (1 block, 1024 threads) ---------------------
__global__ void __launch_bounds__(1024) final_kernel(const int* __restrict__ states,
                                                     int n_states,
                                                     const int* __restrict__ actions,
                                                     const float* __restrict__ Wfc,
                                                     const float* __restrict__ bfc,
                                                     float* __restrict__ out)
{
    __shared__ int   smax[F];
    __shared__ float red[F];
    int tid  = threadIdx.x;
    int wid  = tid >> 5;
    int lane = tid & 31;

    if (tid < F) smax[tid] = 0;        // 0.0f bits; h2 is post-ReLU (>= 0)
    __syncthreads();

    float4 m = make_float4(0.f, 0.f, 0.f, 0.f);
    for (int s = wid; s < n_states; s += 32) {
        float4 v = ((const float4*)g_h2)[states[s] * 32 + lane];
        m.x = fmaxf(m.x, v.x); m.y = fmaxf(m.y, v.y);
        m.z = fmaxf(m.z, v.z); m.w = fmaxf(m.w, v.w);
    }
    atomicMax(&smax[lane * 4 + 0], __float_as_int(m.x));
    atomicMax(&smax[lane * 4 + 1], __float_as_int(m.y));
    atomicMax(&smax[lane * 4 + 2], __float_as_int(m.z));
    atomicMax(&smax[lane * 4 + 3], __float_as_int(m.w));
    __syncthreads();

    if (tid < F) {
        float mm = __int_as_float(smax[tid]);
        float av = g_h2[actions[0] * F + tid];
        red[tid] = mm * Wfc[tid] + av * Wfc[F + tid];
    }
    __syncthreads();
    for (int d = 64; d > 0; d >>= 1) {
        if (tid < d) red[tid] += red[tid + d];
        __syncthreads();
    }
    if (tid == 0) out[0] = red[0] + bfc[0];
}

// ---------------- launch ----------------
extern "C" void kernel_launch(void* const* d_in, const int* in_sizes, int n_in,
                              void* d_out, int out_size) {
    const float* x      = (const float*)d_in[0];
    const int*   esrc   = (const int*)d_in[1];
    const int*   edst   = (const int*)d_in[2];
    const int*   states = (const int*)d_in[3];
    const int*   actions= (const int*)d_in[4];
    const float* W1s    = (const float*)d_in[5];
    const float* W1n    = (const float*)d_in[6];
    const float* b1     = (const float*)d_in[7];
    const float* W2s    = (const float*)d_in[8];
    const float* W2n    = (const float*)d_in[9];
    const float* b2     = (const float*)d_in[10];
    const float* Wfc    = (const float*)d_in[11];
    const float* bfc    = (const float*)d_in[12];
    float* out = (float*)d_out;
    int n_states = in_sizes[3];

    int *list1_p, *list2_p, *n1_p, *n2_p, *ne2_p, *deg1_p, *deg2_p;
    int2 *elist2_p;
    float *agg1_p, *agg2_p, *h1_p, *h2_p;
    cudaGetSymbolAddress((void**)&list1_p,  g_list1);
    cudaGetSymbolAddress((void**)&list2_p,  g_list2);
    cudaGetSymbolAddress((void**)&n1_p,     g_n1);
    cudaGetSymbolAddress((void**)&n2_p,     g_n2);
    cudaGetSymbolAddress((void**)&ne2_p,    g_ne2);
    cudaGetSymbolAddress((void**)&deg1_p,   g_deg1);
    cudaGetSymbolAddress((void**)&deg2_p,   g_deg2);
    cudaGetSymbolAddress((void**)&elist2_p, g_elist2);
    cudaGetSymbolAddress((void**)&agg1_p,   g_agg1);
    cudaGetSymbolAddress((void**)&agg2_p,   g_agg2);
    cudaGetSymbolAddress((void**)&h1_p,     g_h1);
    cudaGetSymbolAddress((void**)&h2_p,     g_h2);

    const int pass_blocks = (QUADS + 255) / 256;   // 782

    // frontier construction
    init_kernel<<<1, 512>>>(states, n_states, actions);
    passA_kernel<<<pass_blocks, 256>>>(esrc, edst);

    // layer 1: fused filter + aggregation, then GEMM (re-zeroes agg1)
    filter_agg1_kernel<<<1024, 256>>>(esrc, edst, x);
    gemm_list_kernel<<<(N_NODES + MT - 1) / MT, 128>>>(list1_p, n1_p, x, agg1_p, deg1_p,
                                                       W1s, W1n, b1, h1_p);

    // layer 2: aggregation over elist2, then GEMM (re-zeroes agg2)
    edge_agg_kernel<<<512, 256>>>(elist2_p, ne2_p, h1_p, agg2_p);
    gemm_list_kernel<<<9, 128>>>(list2_p, n2_p, h1_p, agg2_p, deg2_p,
                                 W2s, W2n, b2, h2_p);

    // readout
    final_kernel<<<1, 1024>>>(states, n_states, actions, Wfc, bfc, out);
}

// round 13
// speedup vs baseline: 1.9032x; 1.1771x over previous
#include <cuda_runtime.h>

#define N_NODES 50000
#define N_EDGES 800000
#define QUADS   (N_EDGES / 4)
#define F 128
#define BM_WORDS ((N_NODES + 31) / 32)

// ---- scratch (static device arrays; zero-initialized; no allocation allowed) ----
__device__ unsigned g_bm1[BM_WORDS];
__device__ unsigned g_bm2[BM_WORDS];
__device__ int   g_list1[N_NODES];
__device__ int   g_list2[512];
__device__ int   g_deg1[N_NODES];
__device__ int   g_deg2[N_NODES];
__device__ int2  g_elist2[N_EDGES];
__device__ int   g_n1, g_n2, g_ne2;
__device__ float g_agg1[N_NODES * F];   // invariant: zero at call entry (gemm re-zeroes)
__device__ float g_agg2[N_NODES * F];   // invariant: zero at call entry (gemm re-zeroes)
__device__ float g_h1[N_NODES * F];
__device__ float g_h2[N_NODES * F];

__device__ __forceinline__ bool bm_test(const unsigned* bm, int n) {
    return (bm[n >> 5] >> (n & 31)) & 1u;
}

// ---------------- init: zero bitmaps+counters, insert S2 seeds (1 block) -------
__global__ void __launch_bounds__(512) init_kernel(const int* __restrict__ states,
                                                   int n_states,
                                                   const int* __restrict__ actions) {
    int tid = threadIdx.x;
    for (int i = tid; i < BM_WORDS; i += 512) { g_bm1[i] = 0u; g_bm2[i] = 0u; }
    if (tid == 0) { g_n1 = 0; g_n2 = 0; g_ne2 = 0; }
    __syncthreads();
    for (int t = tid; t <= n_states; t += 512) {
        int node = (t < n_states) ? states[t] : actions[0];
        unsigned bit = 1u << (node & 31);
        unsigned old2 = atomicOr(&g_bm2[node >> 5], bit);
        if (!(old2 & bit)) {
            int p = atomicAdd(&g_n2, 1);
            g_list2[p] = node;
            g_deg2[node] = 0;
        }
        unsigned old1 = atomicOr(&g_bm1[node >> 5], bit);
        if (!(old1 & bit)) {
            int p = atomicAdd(&g_n1, 1);
            g_list1[p] = node;
            g_deg1[node] = 0;
        }
    }
}

// ---------------- pass A: edges into S2 -> elist2 (+deg2), sources -> S1 -------
__global__ void __launch_bounds__(256) passA_kernel(const int* __restrict__ src,
                                                    const int* __restrict__ dst) {
    __shared__ int s_cnt, s_base;
    if (threadIdx.x == 0) s_cnt = 0;
    __syncthreads();

    int i4 = blockIdx.x * blockDim.x + threadIdx.x;
    int lane = threadIdx.x & 31;
    bool valid = (i4 * 4 < N_EDGES);
    int4 d4 = valid ? ((const int4*)dst)[i4] : make_int4(0, 0, 0, 0);
    int4 s4 = valid ? ((const int4*)src)[i4] : make_int4(0, 0, 0, 0);
    int dv[4] = {d4.x, d4.y, d4.z, d4.w};
    int sv[4] = {s4.x, s4.y, s4.z, s4.w};
    bool pass[4];
    int my = 0;
#pragma unroll
    for (int j = 0; j < 4; j++) {
        pass[j] = valid && bm_test(g_bm2, dv[j]);
        my += pass[j] ? 1 : 0;
    }
    int scan = my;
#pragma unroll
    for (int d = 1; d < 32; d <<= 1) {
        int t = __shfl_up_sync(0xffffffff, scan, d);
        if (lane >= d) scan += t;
    }
    int wtotal = __shfl_sync(0xffffffff, scan, 31);
    int wbase = 0;
    if (lane == 31 && wtotal > 0) wbase = atomicAdd(&s_cnt, wtotal);
    wbase = __shfl_sync(0xffffffff, wbase, 31);
    int my_off = wbase + scan - my;
    __syncthreads();
    if (threadIdx.x == 0) s_base = (s_cnt > 0) ? atomicAdd(&g_ne2, s_cnt) : 0;
    __syncthreads();
    int p = s_base + my_off;
#pragma unroll
    for (int j = 0; j < 4; j++) {
        if (pass[j]) {
            g_elist2[p++] = make_int2(sv[j], dv[j]);
            atomicAdd(&g_deg2[dv[j]], 1);
            unsigned bit = 1u << (sv[j] & 31);
            unsigned old = atomicOr(&g_bm1[sv[j] >> 5], bit);
            if (!(old & bit)) {
                int q = atomicAdd(&g_n1, 1);
                g_list1[q] = sv[j];
                g_deg1[sv[j]] = 0;
            }
        }
    }
}

// ------- fused filter + layer-1 aggregation: ballot over bm1, warp red --------
__global__ void __launch_bounds__(256) filter_agg1_kernel(const int* __restrict__ src,
                                                          const int* __restrict__ dst,
                                                          const float* __restrict__ x) {
    int gw   = (blockIdx.x * blockDim.x + threadIdx.x) >> 5;
    int nw   = ((int)gridDim.x * blockDim.x) >> 5;
    int lane = threadIdx.x & 31;
    for (int base = gw * 32; base < N_EDGES; base += nw * 32) {
        int e = base + lane;
        int d = 0, s = 0;
        bool p = false;
        if (e < N_EDGES) {
            d = dst[e];
            p = bm_test(g_bm1, d);
        }
        unsigned mask = __ballot_sync(0xffffffff, p);
        if (p) s = src[e];
        while (mask) {
            int b = __ffs(mask) - 1;
            mask &= mask - 1;
            int ss = __shfl_sync(0xffffffff, s, b);
            int dd = __shfl_sync(0xffffffff, d, b);
            float4 v = ((const float4*)x)[ss * 32 + lane];
            float* a = &g_agg1[dd * F + lane * 4];
            asm volatile("red.global.add.v4.f32 [%0], {%1, %2, %3, %4};"
                         :: "l"(a), "f"(v.x), "f"(v.y), "f"(v.z), "f"(v.w) : "memory");
            if (lane == (unsigned)b) atomicAdd(&g_deg1[dd], 1);
        }
    }
}

// ---------------- edge aggregation for layer 2: warp per edge ------------------
__global__ void edge_agg_kernel(const int2* __restrict__ elist, const int* __restrict__ ne_p,
                                const float* __restrict__ feat, float* __restrict__ agg) {
    int ne = *ne_p;
    int nwarps = (gridDim.x * blockDim.x) >> 5;
    int warp = (blockIdx.x * blockDim.x + threadIdx.x) >> 5;
    int lane = threadIdx.x & 31;
    for (int j = warp; j < ne; j += nwarps) {
        int2 e = elist[j];
        float4 v = ((const float4*)feat)[e.x * 32 + lane];
        float* a = &agg[e.y * F + lane * 4];
        asm volatile("red.global.add.v4.f32 [%0], {%1, %2, %3, %4};"
                     :: "l"(a), "f"(v.x), "f"(v.y), "f"(v.z), "f"(v.w) : "memory");
    }
}

// ------- gathered fused SAGE GEMM: K-split over 2 warpgroups + reg prefetch ----
// out[node] = relu(feat[node]@Ws^T + (agg[node]/max(deg,1))@Wn^T + b)
// wg0: self half (feat,Ws).  wg1: neighbor half (agg,Wn; 1/deg fused).
// Each wg: 4 kt chunks, 128 threads, 4x8 accumulators, reg-prefetch double-buffer.
// Combine through smem; wg0 does bias+relu+store; wg1 re-zeroes agg rows.
#define MT 32
#define KT 32

__global__ void __launch_bounds__(256) gemm_list_kernel(
    const int* __restrict__ list, const int* __restrict__ count_p,
    const float* __restrict__ feat, float* __restrict__ agg,
    const int* __restrict__ deg,
    const float* __restrict__ Ws, const float* __restrict__ Wn,
    const float* __restrict__ bias, float* __restrict__ out)
{
    int count = *count_p;
    int ntiles = (count + MT - 1) / MT;
    if (blockIdx.x >= ntiles) return;

    __shared__ int   rows[MT];
    __shared__ float invs[MT];
    __shared__ float As[2][KT][MT + 4];
    __shared__ float Bs[2][KT][128 + 4];

    int tid  = threadIdx.x;
    int wg   = tid >> 7;          // 0 or 1
    int wtid = tid & 127;
    int m0   = blockIdx.x * MT;
    int r0   = (wtid >> 4) * 4;   // 0..28 step 4
    int c0   = (wtid & 15) * 8;   // 0..120 step 8

    if (tid < MT) {
        int nd = (m0 + tid < count) ? list[m0 + tid] : -1;
        rows[tid] = nd;
        invs[tid] = (nd >= 0) ? 1.0f / (float)max(deg[nd], 1) : 0.f;
    }
    __syncthreads();

    const float* A = wg ? agg : feat;
    const float* W = wg ? Wn : Ws;

    // per-thread tile fragments (A: 2 float4, W: 8 float4)
    int a_row[2], a_kq[2];
#pragma unroll
    for (int i = 0; i < 2; i++) { int v = wtid + 128 * i; a_row[i] = v >> 3; a_kq[i] = v & 7; }

    float4 pa[2], pw[8];
    // prefetch kt=0
#pragma unroll
    for (int i = 0; i < 2; i++) {
        int nd = rows[a_row[i]];
        pa[i] = make_float4(0.f, 0.f, 0.f, 0.f);
        if (nd >= 0) pa[i] = ((const float4*)A)[nd * 32 + a_kq[i]];
    }
#pragma unroll
    for (int i = 0; i < 8; i++) {
        int v = wtid + 128 * i;
        pw[i] = ((const float4*)W)[(v >> 3) * 32 + (v & 7)];
    }

    float acc[4][8];
#pragma unroll
    for (int m = 0; m < 4; m++)
#pragma unroll
        for (int n = 0; n < 8; n++) acc[m][n] = 0.f;

#pragma unroll 1
    for (int kt = 0; kt < 4; kt++) {
        // store prefetched fragments to smem (scale agg half by 1/deg)
#pragma unroll
        for (int i = 0; i < 2; i++) {
            float sc = wg ? invs[a_row[i]] : 1.0f;
            As[wg][a_kq[i] * 4 + 0][a_row[i]] = pa[i].x * sc;
            As[wg][a_kq[i] * 4 + 1][a_row[i]] = pa[i].y * sc;
            As[wg][a_kq[i] * 4 + 2][a_row[i]] = pa[i].z * sc;
            As[wg][a_kq[i] * 4 + 3][a_row[i]] = pa[i].w * sc;
        }
#pragma unroll
        for (int i = 0; i < 8; i++) {
            int v = wtid + 128 * i;
            Bs[wg][(v & 7) * 4 + 0][v >> 3] = pw[i].x;
            Bs[wg][(v & 7) * 4 + 1][v >> 3] = pw[i].y;
            Bs[wg][(v & 7) * 4 + 2][v >> 3] = pw[i].z;
            Bs[wg][(v & 7) * 4 + 3][v >> 3] = pw[i].w;
        }
        __syncthreads();

        // prefetch kt+1 while computing kt
        if (kt < 3) {
            int kb4 = (kt + 1) * 8;
#pragma unroll
            for (int i = 0; i < 2; i++) {
                int nd = rows[a_row[i]];
                pa[i] = make_float4(0.f, 0.f, 0.f, 0.f);
                if (nd >= 0) pa[i] = ((const float4*)A)[nd * 32 + kb4 + a_kq[i]];
            }
#pragma unroll
            for (int i = 0; i < 8; i++) {
                int v = wtid + 128 * i;
                pw[i] = ((const float4*)W)[(v >> 3) * 32 + kb4 + (v & 7)];
            }
        }

#pragma unroll
        for (int k = 0; k < KT; k++) {
            float4 a4 = *(const float4*)&As[wg][k][r0];
            float4 b0 = *(const float4*)&Bs[wg][k][c0];
            float4 b1 = *(const float4*)&Bs[wg][k][c0 + 4];
            float am[4] = {a4.x, a4.y, a4.z, a4.w};
            float bn[8] = {b0.x, b0.y, b0.z, b0.w, b1.x, b1.y, b1.z, b1.w};
#pragma unroll
            for (int m = 0; m < 4; m++)
#pragma unroll
                for (int n = 0; n < 8; n++)
                    acc[m][n] += am[m] * bn[n];
        }
        __syncthreads();
    }

    // combine: wg1 stores partials into smem (reuse Bs[1] as 32x132 buffer)
    float* part = &Bs[1][0][0];
    if (wg == 1) {
#pragma unroll
        for (int m = 0; m < 4; m++)
#pragma unroll
            for (int n = 0; n < 8; n++)
                part[(r0 + m) * 132 + c0 + n] = acc[m][n];
    }
    __syncthreads();

    if (wg == 0) {
        float bv[8];
#pragma unroll
        for (int n = 0; n < 8; n++) bv[n] = bias[c0 + n];
#pragma unroll
        for (int m = 0; m < 4; m++) {
            int nd = rows[r0 + m];
            if (nd >= 0) {
                float o[8];
#pragma unroll
                for (int n = 0; n < 8; n++)
                    o[n] = fmaxf(acc[m][n] + part[(r0 + m) * 132 + c0 + n] + bv[n], 0.f);
                float4 o0 = make_float4(o[0], o[1], o[2], o[3]);
                float4 o1 = make_float4(o[4], o[5], o[6], o[7]);
                ((float4*)out)[nd * 32 + (c0 >> 2)]     = o0;
                ((float4*)out)[nd * 32 + (c0 >> 2) + 1] = o1;
            }
        }
    } else {
        // wg1: re-zero consumed agg rows (32 rows x 32 float4, 8 per thread)
#pragma unroll
        for (int i = 0; i < 8; i++) {
            int v   = wtid + 128 * i;
            int row = v >> 5;
            int c   = v & 31;
            int nd  = rows[row];
            if (nd >= 0) ((float4*)agg)[nd * 32 + c] = make_float4(0.f, 0.f, 0.f, 0.f);
        }
    }
}

// ---------------- parallel readout (1 block, 1024 threads) ---------------------
__global__ void __launch_bounds__(1024) final_kernel(const int* __restrict__ states,
                                                     int n_states,
                                                     const int* __restrict__ actions,
                                                     const float* __restrict__ Wfc,
                                                     const float* __restrict__ bfc,
                                                     float* __restrict__ out)
{
    __shared__ int   smax[F];
    __shared__ float red[F];
    int tid  = threadIdx.x;
    int wid  = tid >> 5;
    int lane = tid & 31;

    if (tid < F) smax[tid] = 0;        // 0.0f bits; h2 is post-ReLU (>= 0)
    __syncthreads();

    float4 m = make_float4(0.f, 0.f, 0.f, 0.f);
    for (int s = wid; s < n_states; s += 32) {
        float4 v = ((const float4*)g_h2)[states[s] * 32 + lane];
        m.x = fmaxf(m.x, v.x); m.y = fmaxf(m.y, v.y);
        m.z = fmaxf(m.z, v.z); m.w = fmaxf(m.w, v.w);
    }
    atomicMax(&smax[lane * 4 + 0], __float_as_int(m.x));
    atomicMax(&smax[lane * 4 + 1], __float_as_int(m.y));
    atomicMax(&smax[lane * 4 + 2], __float_as_int(m.z));
    atomicMax(&smax[lane * 4 + 3], __float_as_int(m.w));
    __syncthreads();

    if (tid < F) {
        float mm = __int_as_float(smax[tid]);
        float av = g_h2[actions[0] * F + tid];
        red[tid] = mm * Wfc[tid] + av * Wfc[F + tid];
    }
    __syncthreads();
    for (int d = 64; d > 0; d >>= 1) {
        if (tid < d) red[tid] += red[tid + d];
        __syncthreads();
    }
    if (tid == 0) out[0] = red[0] + bfc[0];
}

// ---------------- launch ----------------
extern "C" void kernel_launch(void* const* d_in, const int* in_sizes, int n_in,
                              void* d_out, int out_size) {
    const float* x      = (const float*)d_in[0];
    const int*   esrc   = (const int*)d_in[1];
    const int*   edst   = (const int*)d_in[2];
    const int*   states = (const int*)d_in[3];
    const int*   actions= (const int*)d_in[4];
    const float* W1s    = (const float*)d_in[5];
    const float* W1n    = (const float*)d_in[6];
    const float* b1     = (const float*)d_in[7];
    const float* W2s    = (const float*)d_in[8];
    const float* W2n    = (const float*)d_in[9];
    const float* b2     = (const float*)d_in[10];
    const float* Wfc    = (const float*)d_in[11];
    const float* bfc    = (const float*)d_in[12];
    float* out = (float*)d_out;
    int n_states = in_sizes[3];

    int *list1_p, *list2_p, *n1_p, *n2_p, *ne2_p, *deg1_p, *deg2_p;
    int2 *elist2_p;
    float *agg1_p, *agg2_p, *h1_p, *h2_p;
    cudaGetSymbolAddress((void**)&list1_p,  g_list1);
    cudaGetSymbolAddress((void**)&list2_p,  g_list2);
    cudaGetSymbolAddress((void**)&n1_p,     g_n1);
    cudaGetSymbolAddress((void**)&n2_p,     g_n2);
    cudaGetSymbolAddress((void**)&ne2_p,    g_ne2);
    cudaGetSymbolAddress((void**)&deg1_p,   g_deg1);
    cudaGetSymbolAddress((void**)&deg2_p,   g_deg2);
    cudaGetSymbolAddress((void**)&elist2_p, g_elist2);
    cudaGetSymbolAddress((void**)&agg1_p,   g_agg1);
    cudaGetSymbolAddress((void**)&agg2_p,   g_agg2);
    cudaGetSymbolAddress((void**)&h1_p,     g_h1);
    cudaGetSymbolAddress((void**)&h2_p,     g_h2);

    const int pass_blocks = (QUADS + 255) / 256;   // 782

    // frontier construction
    init_kernel<<<1, 512>>>(states, n_states, actions);
    passA_kernel<<<pass_blocks, 256>>>(esrc, edst);

    // layer 1: fused filter + aggregation, then GEMM (re-zeroes agg1)
    filter_agg1_kernel<<<1024, 256>>>(esrc, edst, x);
    gemm_list_kernel<<<(N_NODES + MT - 1) / MT, 256>>>(list1_p, n1_p, x, agg1_p, deg1_p,
                                                       W1s, W1n, b1, h1_p);

    // layer 2: aggregation over elist2, then GEMM (re-zeroes agg2)
    edge_agg_kernel<<<512, 256>>>(elist2_p, ne2_p, h1_p, agg2_p);
    gemm_list_kernel<<<9, 256>>>(list2_p, n2_p, h1_p, agg2_p, deg2_p,
                                 W2s, W2n, b2, h2_p);

    // readout
    final_kernel<<<1, 1024>>>(states, n_states, actions, Wfc, bfc, out);
}